// round 4
// baseline (speedup 1.0000x reference)
#include <cuda_runtime.h>
#include <cuda_bf16.h>
#include <cstdint>

// Problem constants
#define NV      8000
#define NVT     20000
#define BATCH   8
#define CSUM    960

// GEMM tiling
#define BM 128
#define BN 128
#define BK 32
#define NTHREADS 256

// Scratch (device globals: allowed, no runtime allocation)
__device__ int   g_idx32[NV];
__device__ float g_wsel[CSUM * NV];   // gathered w, [960][8000]

__device__ __forceinline__ float to_tf32(float x) {
    unsigned u;
    asm("cvt.rna.tf32.f32 %0, %1;" : "=r"(u) : "f"(x));
    return __uint_as_float(u);
}

// ---------------------------------------------------------------------------
// roi dtype sniff: reference asks for int64 but JAX (x64 off) materializes
// int32. View as int32: if underlying is int64, odd positions are high words
// of nonneg values < 2^31 -> always 0. If int32, they are sorted draws from
// [0,20000): ri[7999] ~ 20000, and ri[7]==0 needs >=8 zero draws (P~1e-8).
// All probed positions lie within 32KB, valid for both layouts.
// ---------------------------------------------------------------------------
__device__ __forceinline__ int load_roi(const void* roi, int n) {
    const int* ri = (const int*)roi;
    bool is64 = (ri[1] == 0) & (ri[7] == 0) & (ri[4001] == 0) & (ri[7999] == 0);
    return is64 ? (int)((const long long*)roi)[n] : ri[n];
}

// ---------------------------------------------------------------------------
// Prep: gather w columns and convert roi indices to int32.
// grid = (32, 960), block = 256
// ---------------------------------------------------------------------------
__global__ __launch_bounds__(256) void prep_kernel(
    const void* __restrict__ roi,
    const float* __restrict__ w0, const float* __restrict__ w1,
    const float* __restrict__ w2, const float* __restrict__ w3)
{
    int n = blockIdx.x * 256 + threadIdx.x;
    if (n >= NV) return;
    int row = blockIdx.y;                 // 0..959 (global channel)
    int idx = load_roi(roi, n);
    if (row == 0) g_idx32[n] = idx;

    const float* w; int c;
    if (row < 64)       { w = w0; c = row;        }
    else if (row < 192) { w = w1; c = row - 64;   }
    else if (row < 448) { w = w2; c = row - 192;  }
    else                { w = w3; c = row - 448;  }
    g_wsel[(size_t)row * NV + n] = w[(size_t)c * NVT + idx];
}

// ---------------------------------------------------------------------------
// Fused gather + TF32 GEMM + w-scale epilogue.
//   A  = fmap layer  [M x K] row-major, M = 8*C, K = h*h
//   B[k][n] = leaky_relu(RF[k*20000 + idx[n]])
//   out[(b*960 + off + c)*8000 + n] = (A@B)[m][n] * wsel[off+c][n],  m=b*C+c
// block = 256 threads (8 warps: 2 along M x 4 along N, warp tile 64x32)
// grid  = (M/128, ceil(8000/128))  -> x fast = M-blocks share B panel in L2
// ---------------------------------------------------------------------------
__global__ __launch_bounds__(NTHREADS) void gemm_layer_kernel(
    const float* __restrict__ A,
    const float* __restrict__ RF,
    float* __restrict__ out,
    int K, int cShift /*log2(C)*/, int off)
{
    __shared__ float As[BM * 36];   // [row][k], stride 36 -> conflict-free frags
    __shared__ float Bs[BK * 136];  // [k][n],  stride 136 -> conflict-free frags

    const int tid  = threadIdx.x;
    const int m0   = blockIdx.x * BM;
    const int n0   = blockIdx.y * BN;
    const int lane = tid & 31;
    const int warp = tid >> 5;
    const int g    = lane >> 2;     // groupID 0..7
    const int t    = lane & 3;      // thread-in-group 0..3
    const int warpM = warp >> 2;    // 0..1
    const int warpN = warp & 3;     // 0..3

    float acc[4][4][4];             // [mFrag][nFrag][reg]
    #pragma unroll
    for (int i = 0; i < 4; i++)
        #pragma unroll
        for (int j = 0; j < 4; j++)
            #pragma unroll
            for (int r = 0; r < 4; r++) acc[i][j][r] = 0.f;

    // B gather: each thread owns one column of the tile (nb), two k-phases
    const int nb   = tid & 127;
    const int kb   = tid >> 7;           // 0 or 1
    const int ncol = n0 + nb;
    const int col  = (ncol < NV) ? g_idx32[ncol] : 0;
    const float* colPtr = RF + col;

    for (int k0 = 0; k0 < K; k0 += BK) {
        // ---- load A tile 128x32 (tf32-converted), coalesced ----
        #pragma unroll
        for (int i = 0; i < 16; i++) {
            int e  = tid + NTHREADS * i;   // 0..4095
            int r  = e >> 5;
            int kk = e & 31;
            int kg = k0 + kk;
            float v = (kg < K) ? A[(size_t)(m0 + r) * K + kg] : 0.f;
            As[r * 36 + kk] = to_tf32(v);
        }
        // ---- gather B tile 32x128 + leaky_relu + tf32 ----
        #pragma unroll
        for (int j = 0; j < 16; j++) {
            int kk = kb + 2 * j;
            int kg = k0 + kk;
            float v = 0.f;
            if (kg < K && ncol < NV) v = colPtr[(size_t)kg * NVT];
            v = (v > 0.f) ? v : 0.01f * v;
            Bs[kk * 136 + nb] = to_tf32(v);
        }
        __syncthreads();

        #pragma unroll
        for (int kk = 0; kk < BK; kk += 8) {
            unsigned a[4][4];
            #pragma unroll
            for (int mf = 0; mf < 4; mf++) {
                int r0 = warpM * 64 + mf * 16 + g;
                a[mf][0] = __float_as_uint(As[r0 * 36 + kk + t]);
                a[mf][1] = __float_as_uint(As[(r0 + 8) * 36 + kk + t]);
                a[mf][2] = __float_as_uint(As[r0 * 36 + kk + t + 4]);
                a[mf][3] = __float_as_uint(As[(r0 + 8) * 36 + kk + t + 4]);
            }
            unsigned b[4][2];
            #pragma unroll
            for (int nf = 0; nf < 4; nf++) {
                int c0 = warpN * 32 + nf * 8 + g;
                b[nf][0] = __float_as_uint(Bs[(kk + t) * 136 + c0]);
                b[nf][1] = __float_as_uint(Bs[(kk + t + 4) * 136 + c0]);
            }
            #pragma unroll
            for (int mf = 0; mf < 4; mf++)
                #pragma unroll
                for (int nf = 0; nf < 4; nf++) {
                    asm volatile(
                        "mma.sync.aligned.m16n8k8.row.col.f32.tf32.tf32.f32 "
                        "{%0,%1,%2,%3}, {%4,%5,%6,%7}, {%8,%9}, {%0,%1,%2,%3};"
                        : "+f"(acc[mf][nf][0]), "+f"(acc[mf][nf][1]),
                          "+f"(acc[mf][nf][2]), "+f"(acc[mf][nf][3])
                        : "r"(a[mf][0]), "r"(a[mf][1]), "r"(a[mf][2]), "r"(a[mf][3]),
                          "r"(b[nf][0]), "r"(b[nf][1]));
                }
        }
        __syncthreads();
    }

    // ---- epilogue: scale by gathered w, scatter rows into concat layout ----
    const int cMask = (1 << cShift) - 1;
    #pragma unroll
    for (int mf = 0; mf < 4; mf++) {
        #pragma unroll
        for (int half = 0; half < 2; half++) {
            int m   = m0 + warpM * 64 + mf * 16 + g + half * 8;
            int c   = m & cMask;
            int bI  = m >> cShift;
            const float* wrow = g_wsel + (size_t)(off + c) * NV;
            float* orow = out + ((size_t)bI * CSUM + off + c) * NV;
            #pragma unroll
            for (int nf = 0; nf < 4; nf++) {
                int n = n0 + warpN * 32 + nf * 8 + t * 2;
                if (n < NV) {   // n even, pair never straddles 8000
                    float2 wv = *(const float2*)(wrow + n);
                    float2 res;
                    res.x = acc[mf][nf][half * 2 + 0] * wv.x;
                    res.y = acc[mf][nf][half * 2 + 1] * wv.y;
                    *(float2*)(orow + n) = res;
                }
            }
        }
    }
}

// ---------------------------------------------------------------------------
extern "C" void kernel_launch(void* const* d_in, const int* in_sizes, int n_in,
                              void* d_out, int out_size)
{
    // Identify inputs by element count (all 13 sizes are distinct).
    static const int fsz[4] = {1605632,  802816,  401408,  200704};
    static const int rsz[4] = {62720000, 15680000, 3920000, 980000};
    static const int wsz[4] = {1280000,  2560000,  5120000, 10240000};

    const float* F[4]  = {nullptr, nullptr, nullptr, nullptr};
    const float* RF[4] = {nullptr, nullptr, nullptr, nullptr};
    const float* W[4]  = {nullptr, nullptr, nullptr, nullptr};
    const void* roi = nullptr;

    for (int i = 0; i < n_in; i++) {
        int s = in_sizes[i];
        if (s == NV) { roi = d_in[i]; continue; }
        for (int j = 0; j < 4; j++) {
            if (s == fsz[j]) F[j]  = (const float*)d_in[i];
            if (s == rsz[j]) RF[j] = (const float*)d_in[i];
            if (s == wsz[j]) W[j]  = (const float*)d_in[i];
        }
    }

    float* out = (float*)d_out;

    // Prep: idx32 + wsel gather
    {
        dim3 grid((NV + 255) / 256, CSUM);
        prep_kernel<<<grid, 256>>>(roi, W[0], W[1], W[2], W[3]);
    }

    // Per-layer GEMMs
    static const int Cs[4]   = {64, 128, 256, 512};
    static const int cSh[4]  = {6, 7, 8, 9};
    static const int Ks[4]   = {3136, 784, 196, 49};
    static const int offs[4] = {0, 64, 192, 448};

    for (int l = 0; l < 4; l++) {
        int M = BATCH * Cs[l];
        dim3 grid(M / BM, (NV + BN - 1) / BN);
        gemm_layer_kernel<<<grid, NTHREADS>>>(F[l], RF[l], out, Ks[l], cSh[l], offs[l]);
    }
}

// round 6
// speedup vs baseline: 1.3177x; 1.3177x over previous
#include <cuda_runtime.h>
#include <cuda_bf16.h>
#include <cstdint>

// Problem constants
#define NV      8000
#define NVP     8064          // NV padded to multiple of BN (and 16B)
#define NVT     20000
#define BATCH   8
#define CSUM    960
#define KPAD_MAX 3136

// GEMM tiling
#define BM 128
#define BN 128
#define BK 32
#define NTHREADS 256
#define NSTAGES 3

#define AS_STRIDE 36
#define BS_STRIDE 136
#define A_STAGE (BM * AS_STRIDE)          // 4608 floats
#define B_STAGE (BK * BS_STRIDE)          // 4352 floats
#define STAGE_FLOATS (A_STAGE + B_STAGE)  // 8960 floats = 35840 B

// Scratch (device globals: allowed, no runtime allocation)
__device__ int   g_idx32[NV];
__device__ float g_wsel[CSUM * NV];            // gathered w, [960][8000]
__device__ float g_A[1605632];                 // tf32(fmap), [M, K_pad] (max layer0)
__device__ float g_B[(size_t)KPAD_MAX * NVP];  // tf32(leaky(gathered rf)), [K_pad, NVP]

__device__ __forceinline__ float to_tf32(float x) {
    unsigned u;
    asm("cvt.rna.tf32.f32 %0, %1;" : "=r"(u) : "f"(x));
    return __uint_as_float(u);
}

// ---------------------------------------------------------------------------
// roi dtype sniff: reference asks int64, but JAX (x64 off) materializes int32.
// View as int32: if int64, odd positions are high words of nonneg < 2^31 -> 0.
// If int32, they're sorted draws from [0,20000) (P[all probed zero] ~ 1e-8).
// ---------------------------------------------------------------------------
__device__ __forceinline__ int load_roi(const void* roi, int n) {
    const int* ri = (const int*)roi;
    bool is64 = (ri[1] == 0) & (ri[7] == 0) & (ri[4001] == 0) & (ri[7999] == 0);
    return is64 ? (int)((const long long*)roi)[n] : ri[n];
}

// ---------------------------------------------------------------------------
// Prep 1: idx32 + w gather.  grid = (32, 240), 4 rows per block.
// ---------------------------------------------------------------------------
__global__ __launch_bounds__(256) void prep_w_kernel(
    const void* __restrict__ roi,
    const float* __restrict__ w0, const float* __restrict__ w1,
    const float* __restrict__ w2, const float* __restrict__ w3)
{
    int n = blockIdx.x * 256 + threadIdx.x;
    if (n >= NV) return;
    int idx = load_roi(roi, n);
    if (blockIdx.y == 0) g_idx32[n] = idx;

    #pragma unroll
    for (int rr = 0; rr < 4; rr++) {
        int row = blockIdx.y * 4 + rr;      // 0..959
        const float* w; int c;
        if (row < 64)       { w = w0; c = row;        }
        else if (row < 192) { w = w1; c = row - 64;   }
        else if (row < 448) { w = w2; c = row - 192;  }
        else                { w = w3; c = row - 448;  }
        g_wsel[(size_t)row * NV + n] = w[(size_t)c * NVT + idx];
    }
}

// ---------------------------------------------------------------------------
// Prep 2: A panel -> tf32, zero-padded to K_pad.  grid = ceil(M*K_pad/1024), 4/thread.
// ---------------------------------------------------------------------------
__global__ __launch_bounds__(256) void prep_a_kernel(
    const float* __restrict__ A, int M, int K, int K_pad)
{
    int base = (blockIdx.x * 256 + threadIdx.x) * 4;
    #pragma unroll
    for (int j = 0; j < 4; j++) {
        int e = base + j;
        if (e >= M * K_pad) return;
        int r = e / K_pad, k = e - r * K_pad;
        g_A[e] = (k < K) ? to_tf32(A[(size_t)r * K + k]) : 0.f;
    }
}

// ---------------------------------------------------------------------------
// Prep 3: B panel = tf32(leaky(rf gather)), zero-padded.  grid = (32, K_pad/4).
// ---------------------------------------------------------------------------
__global__ __launch_bounds__(256) void prep_b_kernel(
    const float* __restrict__ RF, int K, int K_pad)
{
    int n = blockIdx.x * 256 + threadIdx.x;
    if (n >= NVP) return;
    int idx = (n < NV) ? g_idx32[n] : 0;
    #pragma unroll
    for (int kk = 0; kk < 4; kk++) {
        int k = blockIdx.y * 4 + kk;
        if (k >= K_pad) return;
        float v = 0.f;
        if (k < K && n < NV) {
            float x = RF[(size_t)k * NVT + idx];
            x = (x > 0.f) ? x : 0.01f * x;
            v = to_tf32(x);
        }
        g_B[(size_t)k * NVP + n] = v;
    }
}

// ---------------------------------------------------------------------------
// Dense TF32 GEMM, 3-stage cp.async pipeline, w-scale epilogue.
//   g_A [M, K_pad] tf32,  g_B [K_pad, NVP] tf32 (leaky pre-applied)
// NOTE: g_A/g_B referenced directly in device code (device-global symbols must
// NOT be passed as host-side kernel args — that was the R5 bug).
// block = 256 (8 warps: 2M x 4N, warp tile 64x32); grid = (M/128, 63)
// ---------------------------------------------------------------------------
__global__ __launch_bounds__(NTHREADS, 2) void gemm_pipe_kernel(
    float* __restrict__ out,
    int K_pad, int cShift, int off)
{
    extern __shared__ float smem[];
    const float* __restrict__ A = g_A;
    const float* __restrict__ B = g_B;

    const int tid  = threadIdx.x;
    const int m0   = blockIdx.x * BM;
    const int n0   = blockIdx.y * BN;
    const int lane = tid & 31;
    const int warp = tid >> 5;
    const int g    = lane >> 2;
    const int t    = lane & 3;
    const int warpM = warp >> 2;
    const int warpN = warp & 3;
    const int niter = K_pad / BK;

    float acc[4][4][4];
    #pragma unroll
    for (int i = 0; i < 4; i++)
        #pragma unroll
        for (int j = 0; j < 4; j++)
            #pragma unroll
            for (int r = 0; r < 4; r++) acc[i][j][r] = 0.f;

    // --- async tile loader for iteration `it` ---
    auto issue = [&](int it) {
        int s = it % NSTAGES;
        float* As = smem + s * STAGE_FLOATS;
        float* Bs = As + A_STAGE;
        int k0 = it * BK;
        #pragma unroll
        for (int j = 0; j < 4; j++) {               // A: 128x32, 16B chunks
            int e = tid + NTHREADS * j;
            int r = e >> 3, c = e & 7;
            const float* src = A + (size_t)(m0 + r) * K_pad + k0 + c * 4;
            unsigned dst = (unsigned)__cvta_generic_to_shared(&As[r * AS_STRIDE + c * 4]);
            asm volatile("cp.async.cg.shared.global [%0], [%1], 16;" :: "r"(dst), "l"(src));
        }
        #pragma unroll
        for (int j = 0; j < 4; j++) {               // B: 32x128, 16B chunks
            int e = tid + NTHREADS * j;
            int kk = e >> 5, c = e & 31;
            const float* src = B + (size_t)(k0 + kk) * NVP + n0 + c * 4;
            unsigned dst = (unsigned)__cvta_generic_to_shared(&Bs[kk * BS_STRIDE + c * 4]);
            asm volatile("cp.async.cg.shared.global [%0], [%1], 16;" :: "r"(dst), "l"(src));
        }
    };

    // prologue: stages 0..NSTAGES-2
    #pragma unroll
    for (int p = 0; p < NSTAGES - 1; p++) {
        if (p < niter) issue(p);
        asm volatile("cp.async.commit_group;");
    }

    for (int i = 0; i < niter; i++) {
        asm volatile("cp.async.wait_group %0;" :: "n"(NSTAGES - 2));
        __syncthreads();
        if (i + NSTAGES - 1 < niter) issue(i + NSTAGES - 1);
        asm volatile("cp.async.commit_group;");

        const float* As = smem + (i % NSTAGES) * STAGE_FLOATS;
        const float* Bs = As + A_STAGE;

        #pragma unroll
        for (int kk = 0; kk < BK; kk += 8) {
            unsigned a[4][4];
            #pragma unroll
            for (int mf = 0; mf < 4; mf++) {
                int r0 = warpM * 64 + mf * 16 + g;
                a[mf][0] = __float_as_uint(As[r0 * AS_STRIDE + kk + t]);
                a[mf][1] = __float_as_uint(As[(r0 + 8) * AS_STRIDE + kk + t]);
                a[mf][2] = __float_as_uint(As[r0 * AS_STRIDE + kk + t + 4]);
                a[mf][3] = __float_as_uint(As[(r0 + 8) * AS_STRIDE + kk + t + 4]);
            }
            unsigned b[4][2];
            #pragma unroll
            for (int nf = 0; nf < 4; nf++) {
                int c0 = warpN * 32 + nf * 8 + g;
                b[nf][0] = __float_as_uint(Bs[(kk + t) * BS_STRIDE + c0]);
                b[nf][1] = __float_as_uint(Bs[(kk + t + 4) * BS_STRIDE + c0]);
            }
            #pragma unroll
            for (int mf = 0; mf < 4; mf++)
                #pragma unroll
                for (int nf = 0; nf < 4; nf++) {
                    asm volatile(
                        "mma.sync.aligned.m16n8k8.row.col.f32.tf32.tf32.f32 "
                        "{%0,%1,%2,%3}, {%4,%5,%6,%7}, {%8,%9}, {%0,%1,%2,%3};"
                        : "+f"(acc[mf][nf][0]), "+f"(acc[mf][nf][1]),
                          "+f"(acc[mf][nf][2]), "+f"(acc[mf][nf][3])
                        : "r"(a[mf][0]), "r"(a[mf][1]), "r"(a[mf][2]), "r"(a[mf][3]),
                          "r"(b[nf][0]), "r"(b[nf][1]));
                }
        }
        __syncthreads();
    }

    // ---- epilogue: scale by gathered w, scatter rows into concat layout ----
    const int cMask = (1 << cShift) - 1;
    #pragma unroll
    for (int mf = 0; mf < 4; mf++) {
        #pragma unroll
        for (int half = 0; half < 2; half++) {
            int m   = m0 + warpM * 64 + mf * 16 + g + half * 8;
            int c   = m & cMask;
            int bI  = m >> cShift;
            const float* wrow = g_wsel + (size_t)(off + c) * NV;
            float* orow = out + ((size_t)bI * CSUM + off + c) * NV;
            #pragma unroll
            for (int nf = 0; nf < 4; nf++) {
                int n = n0 + warpN * 32 + nf * 8 + t * 2;
                if (n < NV) {
                    float2 wv = *(const float2*)(wrow + n);
                    float2 res;
                    res.x = acc[mf][nf][half * 2 + 0] * wv.x;
                    res.y = acc[mf][nf][half * 2 + 1] * wv.y;
                    *(float2*)(orow + n) = res;
                }
            }
        }
    }
}

// ---------------------------------------------------------------------------
extern "C" void kernel_launch(void* const* d_in, const int* in_sizes, int n_in,
                              void* d_out, int out_size)
{
    static const int fsz[4] = {1605632,  802816,  401408,  200704};
    static const int rsz[4] = {62720000, 15680000, 3920000, 980000};
    static const int wsz[4] = {1280000,  2560000,  5120000, 10240000};

    const float* F[4]  = {nullptr, nullptr, nullptr, nullptr};
    const float* RF[4] = {nullptr, nullptr, nullptr, nullptr};
    const float* W[4]  = {nullptr, nullptr, nullptr, nullptr};
    const void* roi = nullptr;

    for (int i = 0; i < n_in; i++) {
        int s = in_sizes[i];
        if (s == NV) { roi = d_in[i]; continue; }
        for (int j = 0; j < 4; j++) {
            if (s == fsz[j]) F[j]  = (const float*)d_in[i];
            if (s == rsz[j]) RF[j] = (const float*)d_in[i];
            if (s == wsz[j]) W[j]  = (const float*)d_in[i];
        }
    }

    float* out = (float*)d_out;

    const int SMEM_BYTES = NSTAGES * STAGE_FLOATS * 4;   // 107520
    static bool attr_set = false;
    if (!attr_set) {
        cudaFuncSetAttribute(gemm_pipe_kernel,
                             cudaFuncAttributeMaxDynamicSharedMemorySize, SMEM_BYTES);
        attr_set = true;
    }

    // Prep: idx32 + wsel gather
    prep_w_kernel<<<dim3(32, 240), 256>>>(roi, W[0], W[1], W[2], W[3]);

    static const int Cs[4]    = {64, 128, 256, 512};
    static const int cSh[4]   = {6, 7, 8, 9};
    static const int Ks[4]    = {3136, 784, 196, 49};
    static const int Kpads[4] = {3136, 800, 224, 64};
    static const int offs[4]  = {0, 64, 192, 448};

    for (int l = 0; l < 4; l++) {
        int M = BATCH * Cs[l];
        int K = Ks[l], K_pad = Kpads[l];

        prep_a_kernel<<<(M * K_pad + 1023) / 1024, 256>>>(F[l], M, K, K_pad);
        prep_b_kernel<<<dim3(32, K_pad / 4), 256>>>(RF[l], K, K_pad);

        dim3 grid(M / BM, NVP / BN);
        gemm_pipe_kernel<<<grid, NTHREADS, SMEM_BYTES>>>(
            out, K_pad, cSh[l], offs[l]);
    }
}

// round 7
// speedup vs baseline: 1.3932x; 1.0573x over previous
#include <cuda_runtime.h>
#include <cuda_bf16.h>
#include <cstdint>

// Problem constants
#define NV      8000
#define NVP     8064          // NV padded to multiple of BN (and 16B)
#define NVT     20000
#define BATCH   8
#define CSUM    960
#define KPAD_MAX 3136

// GEMM tiling
#define BM 128
#define BN 128
#define BK 32
#define NTHREADS 256
#define NSTAGES 3

// Pair-interleaved smem layouts (conflict-free LDS.64 fragment loads)
#define AS_STRIDE 40                      // floats per A row
#define BS_STRIDE 264                     // floats per B pair-row
#define A_STAGE (BM * AS_STRIDE)          // 5120 floats
#define B_STAGE (16 * BS_STRIDE)          // 4224 floats (BK/2 pair-rows)
#define STAGE_FLOATS (A_STAGE + B_STAGE)  // 9344 floats = 37376 B

// Scratch (device globals: allowed, no runtime allocation)
__device__ int   g_idx32[NV];
__device__ float g_wsel[CSUM * NV];            // gathered w, [960][8000]
__device__ float g_A[1605632];                 // tf32(fmap), [M][K_pad] k-permuted
__device__ float g_B[(size_t)KPAD_MAX * NVP];  // [K_pad/2 pair-rows][NVP*2]

__device__ __forceinline__ float to_tf32(float x) {
    unsigned u;
    asm("cvt.rna.tf32.f32 %0, %1;" : "=r"(u) : "f"(x));
    return __uint_as_float(u);
}

// ---------------------------------------------------------------------------
// roi dtype sniff: reference asks int64, but JAX (x64 off) materializes int32.
// ---------------------------------------------------------------------------
__device__ __forceinline__ int load_roi(const void* roi, int n) {
    const int* ri = (const int*)roi;
    bool is64 = (ri[1] == 0) & (ri[7] == 0) & (ri[4001] == 0) & (ri[7999] == 0);
    return is64 ? (int)((const long long*)roi)[n] : ri[n];
}

// ---------------------------------------------------------------------------
// Prep 1: idx32 + w gather.  grid = (32, 240), 4 rows per block.
// ---------------------------------------------------------------------------
__global__ __launch_bounds__(256) void prep_w_kernel(
    const void* __restrict__ roi,
    const float* __restrict__ w0, const float* __restrict__ w1,
    const float* __restrict__ w2, const float* __restrict__ w3)
{
    int n = blockIdx.x * 256 + threadIdx.x;
    if (n >= NV) return;
    int idx = load_roi(roi, n);
    if (blockIdx.y == 0) g_idx32[n] = idx;

    #pragma unroll
    for (int rr = 0; rr < 4; rr++) {
        int row = blockIdx.y * 4 + rr;      // 0..959
        const float* w; int c;
        if (row < 64)       { w = w0; c = row;        }
        else if (row < 192) { w = w1; c = row - 64;   }
        else if (row < 448) { w = w2; c = row - 192;  }
        else                { w = w3; c = row - 448;  }
        g_wsel[(size_t)row * NV + n] = w[(size_t)c * NVT + idx];
    }
}

// ---------------------------------------------------------------------------
// Prep 2: A panel -> tf32, k pair-permuted within each 8-block, zero-padded.
// Store position s (within row): within = s%8 = t*2+half -> k = (s&~7)+t+4*half.
// ---------------------------------------------------------------------------
__global__ __launch_bounds__(256) void prep_a_kernel(
    const float* __restrict__ A, int M, int K, int K_pad)
{
    int base = (blockIdx.x * 256 + threadIdx.x) * 4;
    #pragma unroll
    for (int j = 0; j < 4; j++) {
        int e = base + j;
        if (e >= M * K_pad) return;
        int r = e / K_pad, s = e - r * K_pad;
        int within = s & 7;
        int k = (s & ~7) + (within >> 1) + (within & 1) * 4;
        g_A[e] = (k < K) ? to_tf32(A[(size_t)r * K + k]) : 0.f;
    }
}

// ---------------------------------------------------------------------------
// Prep 3: B panel, pair-interleaved: row R = 4*(k/8) + k%4 holds
// float2( tf32(leaky(rf[k][idx[n]])), tf32(leaky(rf[k+4][idx[n]])) ).
// grid = (32, K_pad/8), 4 pair-rows per block; coalesced float2 writes.
// ---------------------------------------------------------------------------
__global__ __launch_bounds__(256) void prep_b_kernel(
    const float* __restrict__ RF, int K, int K_pad)
{
    int n = blockIdx.x * 256 + threadIdx.x;
    if (n >= NVP) return;
    int idx = (n < NV) ? g_idx32[n] : 0;
    #pragma unroll
    for (int rr = 0; rr < 4; rr++) {
        int R = blockIdx.y * 4 + rr;          // pair-row, 0..K_pad/2-1
        int k1 = (R >> 2) * 8 + (R & 3);
        int k2 = k1 + 4;
        float v1 = 0.f, v2 = 0.f;
        if (n < NV) {
            if (k1 < K) {
                float x = RF[(size_t)k1 * NVT + idx];
                v1 = to_tf32((x > 0.f) ? x : 0.01f * x);
            }
            if (k2 < K) {
                float x = RF[(size_t)k2 * NVT + idx];
                v2 = to_tf32((x > 0.f) ? x : 0.01f * x);
            }
        }
        *(float2*)&g_B[((size_t)R * NVP + n) * 2] = make_float2(v1, v2);
    }
}

// ---------------------------------------------------------------------------
// Dense TF32 GEMM, 3-stage cp.async pipeline, LDS.64 fragment loads,
// w-scale epilogue. g_A/g_B referenced directly (device-global symbols).
// block = 256 (8 warps: 2M x 4N, warp tile 64x32); grid = (M/128, 63)
// ---------------------------------------------------------------------------
__global__ __launch_bounds__(NTHREADS, 2) void gemm_pipe_kernel(
    float* __restrict__ out,
    int K_pad, int cShift, int off)
{
    extern __shared__ float smem[];
    const float* __restrict__ A = g_A;
    const float* __restrict__ B = g_B;

    const int tid  = threadIdx.x;
    const int m0   = blockIdx.x * BM;
    const int n0   = blockIdx.y * BN;
    const int lane = tid & 31;
    const int warp = tid >> 5;
    const int g    = lane >> 2;
    const int t    = lane & 3;
    const int warpM = warp >> 2;
    const int warpN = warp & 3;
    const int niter = K_pad / BK;

    float acc[4][4][4];
    #pragma unroll
    for (int i = 0; i < 4; i++)
        #pragma unroll
        for (int j = 0; j < 4; j++)
            #pragma unroll
            for (int r = 0; r < 4; r++) acc[i][j][r] = 0.f;

    // --- async tile loader for iteration `it` ---
    auto issue = [&](int it) {
        int s = it % NSTAGES;
        float* As = smem + s * STAGE_FLOATS;
        float* Bs = As + A_STAGE;
        #pragma unroll
        for (int j = 0; j < 4; j++) {               // A: 128 rows x 32 floats
            int e = tid + NTHREADS * j;             // 1024 chunks of 16B
            int r = e >> 3, c = e & 7;
            const float* src = A + (size_t)(m0 + r) * K_pad + it * BK + c * 4;
            unsigned dst = (unsigned)__cvta_generic_to_shared(&As[r * AS_STRIDE + c * 4]);
            asm volatile("cp.async.cg.shared.global [%0], [%1], 16;" :: "r"(dst), "l"(src));
        }
        #pragma unroll
        for (int j = 0; j < 4; j++) {               // B: 16 pair-rows x 256 floats
            int e = tid + NTHREADS * j;             // 1024 chunks of 16B
            int r = e >> 6, c = e & 63;
            const float* src = B + ((size_t)(16 * it + r) * NVP + n0) * 2 + c * 4;
            unsigned dst = (unsigned)__cvta_generic_to_shared(&Bs[r * BS_STRIDE + c * 4]);
            asm volatile("cp.async.cg.shared.global [%0], [%1], 16;" :: "r"(dst), "l"(src));
        }
    };

    // prologue
    #pragma unroll
    for (int p = 0; p < NSTAGES - 1; p++) {
        if (p < niter) issue(p);
        asm volatile("cp.async.commit_group;");
    }

    for (int i = 0; i < niter; i++) {
        asm volatile("cp.async.wait_group %0;" :: "n"(NSTAGES - 2));
        __syncthreads();
        if (i + NSTAGES - 1 < niter) issue(i + NSTAGES - 1);
        asm volatile("cp.async.commit_group;");

        const float* As = smem + (i % NSTAGES) * STAGE_FLOATS;
        const float* Bs = As + A_STAGE;

        #pragma unroll
        for (int b8 = 0; b8 < 4; b8++) {            // 4 x (k=8) steps
            // A fragments: 8 x LDS.64 (conflict-free, stride 40)
            float2 a0[4], a1[4];
            #pragma unroll
            for (int mf = 0; mf < 4; mf++) {
                int r0 = warpM * 64 + mf * 16 + g;
                a0[mf] = *(const float2*)&As[r0 * AS_STRIDE + b8 * 8 + 2 * t];
                a1[mf] = *(const float2*)&As[(r0 + 8) * AS_STRIDE + b8 * 8 + 2 * t];
            }
            // B fragments: 4 x LDS.64 (conflict-free, stride 264)
            float2 bv[4];
            #pragma unroll
            for (int nf = 0; nf < 4; nf++) {
                int c0 = warpN * 32 + nf * 8 + g;
                bv[nf] = *(const float2*)&Bs[(b8 * 4 + t) * BS_STRIDE + c0 * 2];
            }
            #pragma unroll
            for (int mf = 0; mf < 4; mf++)
                #pragma unroll
                for (int nf = 0; nf < 4; nf++) {
                    asm volatile(
                        "mma.sync.aligned.m16n8k8.row.col.f32.tf32.tf32.f32 "
                        "{%0,%1,%2,%3}, {%4,%5,%6,%7}, {%8,%9}, {%0,%1,%2,%3};"
                        : "+f"(acc[mf][nf][0]), "+f"(acc[mf][nf][1]),
                          "+f"(acc[mf][nf][2]), "+f"(acc[mf][nf][3])
                        : "r"(__float_as_uint(a0[mf].x)), "r"(__float_as_uint(a1[mf].x)),
                          "r"(__float_as_uint(a0[mf].y)), "r"(__float_as_uint(a1[mf].y)),
                          "r"(__float_as_uint(bv[nf].x)), "r"(__float_as_uint(bv[nf].y)));
                }
        }
        __syncthreads();
    }

    // ---- epilogue: scale by gathered w, scatter rows into concat layout ----
    const int cMask = (1 << cShift) - 1;
    #pragma unroll
    for (int mf = 0; mf < 4; mf++) {
        #pragma unroll
        for (int half = 0; half < 2; half++) {
            int m   = m0 + warpM * 64 + mf * 16 + g + half * 8;
            int c   = m & cMask;
            int bI  = m >> cShift;
            const float* wrow = g_wsel + (size_t)(off + c) * NV;
            float* orow = out + ((size_t)bI * CSUM + off + c) * NV;
            #pragma unroll
            for (int nf = 0; nf < 4; nf++) {
                int n = n0 + warpN * 32 + nf * 8 + t * 2;
                if (n < NV) {
                    float2 wv = *(const float2*)(wrow + n);
                    float2 res;
                    res.x = acc[mf][nf][half * 2 + 0] * wv.x;
                    res.y = acc[mf][nf][half * 2 + 1] * wv.y;
                    *(float2*)(orow + n) = res;
                }
            }
        }
    }
}

// ---------------------------------------------------------------------------
extern "C" void kernel_launch(void* const* d_in, const int* in_sizes, int n_in,
                              void* d_out, int out_size)
{
    static const int fsz[4] = {1605632,  802816,  401408,  200704};
    static const int rsz[4] = {62720000, 15680000, 3920000, 980000};
    static const int wsz[4] = {1280000,  2560000,  5120000, 10240000};

    const float* F[4]  = {nullptr, nullptr, nullptr, nullptr};
    const float* RF[4] = {nullptr, nullptr, nullptr, nullptr};
    const float* W[4]  = {nullptr, nullptr, nullptr, nullptr};
    const void* roi = nullptr;

    for (int i = 0; i < n_in; i++) {
        int s = in_sizes[i];
        if (s == NV) { roi = d_in[i]; continue; }
        for (int j = 0; j < 4; j++) {
            if (s == fsz[j]) F[j]  = (const float*)d_in[i];
            if (s == rsz[j]) RF[j] = (const float*)d_in[i];
            if (s == wsz[j]) W[j]  = (const float*)d_in[i];
        }
    }

    float* out = (float*)d_out;

    const int SMEM_BYTES = NSTAGES * STAGE_FLOATS * 4;   // 112128
    static bool attr_set = false;
    if (!attr_set) {
        cudaFuncSetAttribute(gemm_pipe_kernel,
                             cudaFuncAttributeMaxDynamicSharedMemorySize, SMEM_BYTES);
        attr_set = true;
    }

    // Prep: idx32 + wsel gather
    prep_w_kernel<<<dim3(32, 240), 256>>>(roi, W[0], W[1], W[2], W[3]);

    static const int Cs[4]    = {64, 128, 256, 512};
    static const int cSh[4]   = {6, 7, 8, 9};
    static const int Ks[4]    = {3136, 784, 196, 49};
    static const int Kpads[4] = {3136, 800, 224, 64};
    static const int offs[4]  = {0, 64, 192, 448};

    for (int l = 0; l < 4; l++) {
        int M = BATCH * Cs[l];
        int K = Ks[l], K_pad = Kpads[l];

        prep_a_kernel<<<(M * K_pad + 1023) / 1024, 256>>>(F[l], M, K, K_pad);
        prep_b_kernel<<<dim3(32, K_pad / 8), 256>>>(RF[l], K, K_pad);

        dim3 grid(M / BM, NVP / BN);
        gemm_pipe_kernel<<<grid, NTHREADS, SMEM_BYTES>>>(
            out, K_pad, cSh[l], offs[l]);
    }
}

// round 10
// speedup vs baseline: 1.9975x; 1.4337x over previous
#include <cuda_runtime.h>
#include <cuda_fp16.h>
#include <cstdint>

// Problem constants
#define NV      8000
#define NVP     8064          // padded to multiple of BN=128
#define NVT     20000
#define BATCH   8
#define CSUM    960

// GEMM tiling (fp16 mma.sync, BK=64)
#define BM 128
#define BN 128
#define BK 64
#define NTHREADS 256
#define NSTG 3
#define A_ST 16384                         // 128 rows x 64 halves x 2B
#define B_ST 16384
#define STG_BYTES (A_ST + B_ST)            // 32768
#define SMEM_BYTES (NSTG * STG_BYTES)      // 98304

#define SWB(r, ck) ((unsigned)((r) * 128 + ((((ck) ^ ((r) & 7))) << 4)))

// Scratch (device globals: allowed, no runtime allocation)
__device__ int    g_idx32[NV];
__device__ float  g_wsel[CSUM * NV];              // gathered w, [960][8000]
__device__ __half g_Ah[512 * 3136];               // fp16(fmap), [M][K_pad]
__device__ __half g_Bh[(size_t)NVP * 3136];       // fp16(leaky(rf gather)), [n][K_pad]

__device__ __forceinline__ uint32_t smem_u32(const void* p) {
    uint32_t a;
    asm("{ .reg .u64 t; cvta.to.shared.u64 t, %1; cvt.u32.u64 %0, t; }" : "=r"(a) : "l"(p));
    return a;
}

// ---------------------------------------------------------------------------
// roi dtype sniff: reference asks int64, but JAX (x64 off) materializes int32.
// ---------------------------------------------------------------------------
__device__ __forceinline__ int load_roi(const void* roi, int n) {
    const int* ri = (const int*)roi;
    bool is64 = (ri[1] == 0) & (ri[7] == 0) & (ri[4001] == 0) & (ri[7999] == 0);
    return is64 ? (int)((const long long*)roi)[n] : ri[n];
}

// ---------------------------------------------------------------------------
// Prep 1: idx32 + w gather.  grid = (32, 240), 4 rows per block.
// ---------------------------------------------------------------------------
__global__ __launch_bounds__(256) void prep_w_kernel(
    const void* __restrict__ roi,
    const float* __restrict__ w0, const float* __restrict__ w1,
    const float* __restrict__ w2, const float* __restrict__ w3)
{
    int n = blockIdx.x * 256 + threadIdx.x;
    if (n >= NV) return;
    int idx = load_roi(roi, n);
    if (blockIdx.y == 0) g_idx32[n] = idx;

    #pragma unroll
    for (int rr = 0; rr < 4; rr++) {
        int row = blockIdx.y * 4 + rr;
        const float* w; int c;
        if (row < 64)       { w = w0; c = row;        }
        else if (row < 192) { w = w1; c = row - 64;   }
        else if (row < 448) { w = w2; c = row - 192;  }
        else                { w = w3; c = row - 448;  }
        g_wsel[(size_t)row * NV + n] = w[(size_t)c * NVT + idx];
    }
}

// ---------------------------------------------------------------------------
// Prep 2: A -> fp16, [M][K_pad], zero-padded.
// ---------------------------------------------------------------------------
__global__ __launch_bounds__(256) void prep_a_kernel(
    const float* __restrict__ A, int M, int K, int K_pad)
{
    int base = (blockIdx.x * 256 + threadIdx.x) * 4;
    #pragma unroll
    for (int j = 0; j < 4; j++) {
        int e = base + j;
        if (e >= M * K_pad) return;
        int r = e / K_pad, k = e - r * K_pad;
        g_Ah[e] = (k < K) ? __float2half_rn(A[(size_t)r * K + k]) : __float2half_rn(0.f);
    }
}

// ---------------------------------------------------------------------------
// Prep 3: B panel [n][K_pad] fp16 = leaky(rf[k][idx[n]]) via smem transpose.
// Block: 64 n x 32 k.  grid = (NVP/64, K_pad/32).
// ---------------------------------------------------------------------------
__global__ __launch_bounds__(256) void prep_b_kernel(
    const float* __restrict__ RF, int K, int K_pad)
{
    __shared__ float s[64][33];
    int t  = threadIdx.x;
    int n0 = blockIdx.x * 64;
    int k0 = blockIdx.y * 32;

    int n_l = t & 63;
    int kq  = t >> 6;                 // 0..3
    int n   = n0 + n_l;
    int idx = (n < NV) ? g_idx32[n] : 0;
    #pragma unroll
    for (int p = 0; p < 8; p++) {
        int k_l = p * 4 + kq;
        int k   = k0 + k_l;
        float v = 0.f;
        if (k < K && n < NV) {
            float x = RF[(size_t)k * NVT + idx];
            v = (x > 0.f) ? x : 0.01f * x;
        }
        s[n_l][k_l] = v;
    }
    __syncthreads();

    int nr = t >> 2;                  // 0..63
    int q  = t & 3;                   // 0..3
    __half h[8];
    #pragma unroll
    for (int i = 0; i < 8; i++) h[i] = __float2half_rn(s[nr][q * 8 + i]);
    *(uint4*)&g_Bh[(size_t)(n0 + nr) * K_pad + k0 + q * 8] = *(uint4*)h;
}

// ---------------------------------------------------------------------------
// FP16 GEMM (f32 accumulate), BK=64, 3-stage cp.async, ldmatrix fragments,
// w-scale epilogue.  block = 256 (8 warps: 2M x 4N, warp tile 64x32).
// grid = (M/128, 63), x fast -> M-blocks share B panel in L2.
// ---------------------------------------------------------------------------
__global__ __launch_bounds__(NTHREADS, 2) void gemm_fp16_kernel(
    float* __restrict__ out, int K_pad, int cShift, int off)
{
    extern __shared__ __align__(128) char smem[];
    const uint32_t smb = smem_u32(smem);

    const int tid  = threadIdx.x;
    const int m0   = blockIdx.x * BM;
    const int n0   = blockIdx.y * BN;
    const int lane = tid & 31;
    const int warp = tid >> 5;
    const int g    = lane >> 2;
    const int t    = lane & 3;
    const int warpM = warp >> 2;     // 0..1
    const int warpN = warp & 3;      // 0..3
    const int niter = K_pad / BK;

    float acc[4][4][4];
    #pragma unroll
    for (int i = 0; i < 4; i++)
        #pragma unroll
        for (int j = 0; j < 4; j++)
            #pragma unroll
            for (int r = 0; r < 4; r++) acc[i][j][r] = 0.f;

    // --- async tile loader for chunk j (A and B: 128 rows x 8 x 16B each) ---
    auto issue = [&](int j) {
        uint32_t Ab = smb + (j % NSTG) * STG_BYTES;
        uint32_t Bb = Ab + A_ST;
        int k0 = j * BK;
        #pragma unroll
        for (int u = 0; u < 4; u++) {
            int e = tid + NTHREADS * u;           // 0..1023
            int r = e >> 3, ck = e & 7;
            const __half* srcA = g_Ah + (size_t)(m0 + r) * K_pad + k0 + ck * 8;
            asm volatile("cp.async.cg.shared.global [%0], [%1], 16;"
                         :: "r"(Ab + SWB(r, ck)), "l"(srcA));
            const __half* srcB = g_Bh + (size_t)(n0 + r) * K_pad + k0 + ck * 8;
            asm volatile("cp.async.cg.shared.global [%0], [%1], 16;"
                         :: "r"(Bb + SWB(r, ck)), "l"(srcB));
        }
    };

    #pragma unroll
    for (int p = 0; p < NSTG - 1; p++) {
        if (p < niter) issue(p);
        asm volatile("cp.async.commit_group;");
    }

    // ldmatrix lane-address components (constant per thread)
    const int la_row8 = (lane & 7) + ((lane >> 3) & 1) * 8;   // A: row-in-16
    const int la_ckhi = lane >> 4;                             // A: k-chunk sel
    const int lb_row  = (lane & 7) + ((lane >> 4) << 3);       // B: n-in-16
    const int lb_ck   = (lane >> 3) & 1;                       // B: k-chunk sel

    for (int i = 0; i < niter; i++) {
        asm volatile("cp.async.wait_group %0;" :: "n"(NSTG - 2));
        __syncthreads();
        if (i + NSTG - 1 < niter) issue(i + NSTG - 1);
        asm volatile("cp.async.commit_group;");

        uint32_t As = smb + (i % NSTG) * STG_BYTES;
        uint32_t Bs = As + A_ST;

        #pragma unroll
        for (int s = 0; s < 4; s++) {            // 4 x k16 steps
            // A fragments: 4 x ldmatrix.x4
            uint32_t a[4][4];
            #pragma unroll
            for (int mf = 0; mf < 4; mf++) {
                int row = warpM * 64 + mf * 16 + la_row8;
                int ck  = s * 2 + la_ckhi;
                uint32_t ad = As + SWB(row, ck);
                asm volatile("ldmatrix.sync.aligned.m8n8.x4.shared.b16 "
                             "{%0,%1,%2,%3}, [%4];"
                             : "=r"(a[mf][0]), "=r"(a[mf][1]),
                               "=r"(a[mf][2]), "=r"(a[mf][3]) : "r"(ad));
            }
            // B fragments: 2 x ldmatrix.x4 (each covers two n8 tiles x k16)
            uint32_t b[4][2];
            #pragma unroll
            for (int nfp = 0; nfp < 2; nfp++) {
                int row = warpN * 32 + nfp * 16 + lb_row;
                int ck  = s * 2 + lb_ck;
                uint32_t bd = Bs + SWB(row, ck);
                uint32_t r0, r1, r2, r3;
                asm volatile("ldmatrix.sync.aligned.m8n8.x4.shared.b16 "
                             "{%0,%1,%2,%3}, [%4];"
                             : "=r"(r0), "=r"(r1), "=r"(r2), "=r"(r3) : "r"(bd));
                b[nfp * 2 + 0][0] = r0; b[nfp * 2 + 0][1] = r1;
                b[nfp * 2 + 1][0] = r2; b[nfp * 2 + 1][1] = r3;
            }
            #pragma unroll
            for (int mf = 0; mf < 4; mf++)
                #pragma unroll
                for (int nf = 0; nf < 4; nf++) {
                    asm volatile(
                        "mma.sync.aligned.m16n8k16.row.col.f32.f16.f16.f32 "
                        "{%0,%1,%2,%3}, {%4,%5,%6,%7}, {%8,%9}, {%0,%1,%2,%3};"
                        : "+f"(acc[mf][nf][0]), "+f"(acc[mf][nf][1]),
                          "+f"(acc[mf][nf][2]), "+f"(acc[mf][nf][3])
                        : "r"(a[mf][0]), "r"(a[mf][1]), "r"(a[mf][2]), "r"(a[mf][3]),
                          "r"(b[nf][0]), "r"(b[nf][1]));
                }
        }
        __syncthreads();
    }

    // ---- epilogue: scale by gathered w, scatter rows into concat layout ----
    const int cMask = (1 << cShift) - 1;
    #pragma unroll
    for (int mf = 0; mf < 4; mf++) {
        #pragma unroll
        for (int half = 0; half < 2; half++) {
            int m   = m0 + warpM * 64 + mf * 16 + g + half * 8;
            int c   = m & cMask;
            int bI  = m >> cShift;
            const float* wrow = g_wsel + (size_t)(off + c) * NV;
            float* orow = out + ((size_t)bI * CSUM + off + c) * NV;
            #pragma unroll
            for (int nf = 0; nf < 4; nf++) {
                int n = n0 + warpN * 32 + nf * 8 + t * 2;
                if (n < NV) {
                    float2 wv = *(const float2*)(wrow + n);
                    float2 res;
                    res.x = acc[mf][nf][half * 2 + 0] * wv.x;
                    res.y = acc[mf][nf][half * 2 + 1] * wv.y;
                    *(float2*)(orow + n) = res;
                }
            }
        }
    }
}

// ---------------------------------------------------------------------------
extern "C" void kernel_launch(void* const* d_in, const int* in_sizes, int n_in,
                              void* d_out, int out_size)
{
    static const int fsz[4] = {1605632,  802816,  401408,  200704};
    static const int rsz[4] = {62720000, 15680000, 3920000, 980000};
    static const int wsz[4] = {1280000,  2560000,  5120000, 10240000};

    const float* F[4]  = {nullptr, nullptr, nullptr, nullptr};
    const float* RF[4] = {nullptr, nullptr, nullptr, nullptr};
    const float* W[4]  = {nullptr, nullptr, nullptr, nullptr};
    const void* roi = nullptr;

    for (int i = 0; i < n_in; i++) {
        int s = in_sizes[i];
        if (s == NV) { roi = d_in[i]; continue; }
        for (int j = 0; j < 4; j++) {
            if (s == fsz[j]) F[j]  = (const float*)d_in[i];
            if (s == rsz[j]) RF[j] = (const float*)d_in[i];
            if (s == wsz[j]) W[j]  = (const float*)d_in[i];
        }
    }

    float* out = (float*)d_out;

    static bool attr_set = false;
    if (!attr_set) {
        cudaFuncSetAttribute(gemm_fp16_kernel,
                             cudaFuncAttributeMaxDynamicSharedMemorySize, SMEM_BYTES);
        attr_set = true;
    }

    prep_w_kernel<<<dim3(32, 240), 256>>>(roi, W[0], W[1], W[2], W[3]);

    static const int Cs[4]    = {64, 128, 256, 512};
    static const int cSh[4]   = {6, 7, 8, 9};
    static const int Ks[4]    = {3136, 784, 196, 49};
    static const int Kpads[4] = {3136, 832, 256, 64};   // multiples of BK=64
    static const int offs[4]  = {0, 64, 192, 448};

    for (int l = 0; l < 4; l++) {
        int M = BATCH * Cs[l];
        int K = Ks[l], K_pad = Kpads[l];

        prep_a_kernel<<<(M * K_pad + 1023) / 1024, 256>>>(F[l], M, K, K_pad);
        prep_b_kernel<<<dim3(NVP / 64, K_pad / 32), 256>>>(RF[l], K, K_pad);

        dim3 grid(M / BM, NVP / BN);
        gemm_fp16_kernel<<<grid, NTHREADS, SMEM_BYTES>>>(out, K_pad, cSh[l], offs[l]);
    }
}